// round 16
// baseline (speedup 1.0000x reference)
#include <cuda_runtime.h>
#include <cuda_fp16.h>
#include <cstdint>

#define BATCH 32
#define H 512
#define W 512
#define NSTEPS 10
#define NPIX (H * W)
#define TW 128            // tile width
#define TH 64             // tile height
#define OXH 12            // smem col (halves) of local x=0, even
#define OY 10             // smem row of local y=0
#define SPH 152           // smem pitch in halves (304B/row)
#define SROWS 84          // local y in [-10, 74)
#define SMEM_BUFH (SROWS * SPH)   // halves per buffer
#define NTHREADS 512
#define NWARPS (NTHREADS / 32)

__device__ int g_t[BATCH];
__device__ int g_order[BATCH];  // batches sorted by descending t (LPT schedule)

// Normalize t into g_t as int32 (handles int64-vs-int32 materialization of the
// jax reference: if int64 little-endian with values in [0,10), all odd 32-bit
// words of the first 128 bytes are zero). Also builds the LPT batch order.
__global__ void prep_t_kernel(const int* __restrict__ traw) {
    int lane = threadIdx.x;  // 0..31
    int w = traw[lane];
    unsigned oddnz = __ballot_sync(0xffffffffu, ((lane & 1) != 0) && (w != 0));
    int v = (oddnz == 0u) ? traw[2 * lane] : w;
    v = min(max(v, 0), NSTEPS);
    g_t[lane] = v;

    int rank = 0;
#pragma unroll
    for (int j = 0; j < BATCH; j++) {
        int kj = __shfl_sync(0xffffffffu, v, j);
        rank += (kj > v) || (kj == v && j < lane);
    }
    g_order[rank] = lane;
}

__device__ __forceinline__ __half2 u2h(uint32_t u) {
    union { uint32_t u; __half2 h; } v; v.u = u; return v.h;
}
__device__ __forceinline__ uint32_t ld32(const __half* p) {
    return *reinterpret_cast<const uint32_t*>(p);
}

__device__ __forceinline__ __half2 med3h(__half2 a, __half2 b, __half2 c) {
    return __hmax2(__hmin2(a, b), __hmin2(__hmax2(a, b), c));
}
__device__ __forceinline__ void sort3h(__half2 a, __half2 b, __half2 c,
                                       __half2& lo, __half2& md, __half2& hi) {
    __half2 s = __hmin2(a, b);
    __half2 t = __hmax2(a, b);
    lo = __hmin2(s, c);
    hi = __hmax2(t, c);
    md = __hmax2(s, __hmin2(t, c));
}

// One packed output row (2 px): consume prefetched raw words into slot Cc
// (2 PRMT build the shifted windows; edge clamp lives in the per-thread
// selector/offset constants), issue next row's 3 loads early, combine, store.
template <int A, int B, int Cc, bool GM>
__device__ __forceinline__ void row_step(const __half* __restrict__ pn,
                                         uint32_t raw[3],
                                         __half* opS, float* opG,
                                         int x0, int pLoff, uint32_t selL,
                                         int pRoff, uint32_t selR,
                                         __half2 lo[3], __half2 md[3], __half2 hi[3]) {
    __half2 vL = u2h(__byte_perm(raw[0], raw[1], selL));  // (v[x0-1], v[x0])
    __half2 vC = u2h(raw[1]);                             // (v[x0],   v[x0+1])
    __half2 vR = u2h(__byte_perm(raw[1], raw[2], selR));  // (v[x0+1], v[x0+2])
    sort3h(vL, vC, vR, lo[Cc], md[Cc], hi[Cc]);
    uint32_t na = ld32(pn + x0 + pLoff);   // independent: issues early
    uint32_t nb = ld32(pn + x0);
    uint32_t nc = ld32(pn + x0 + pRoff);
    __half2 mn  = __hmax2(__hmax2(lo[A], lo[B]), lo[Cc]);  // max of mins
    __half2 mx  = __hmin2(__hmin2(hi[A], hi[B]), hi[Cc]);  // min of maxs
    __half2 mdv = med3h(md[A], md[B], md[Cc]);             // med of meds
    __half2 res = med3h(mn, mdv, mx);                      // median9
    if (GM) {
        float2 f = __half22float2(res);
        *reinterpret_cast<float2*>(opG) = f;
    } else {
        *reinterpret_cast<__half2*>(opS) = res;
    }
    raw[0] = na; raw[1] = nb; raw[2] = nc;
}

// Median-filter region [rxlo,rxhi)x[rylo,ryhi) from smem cb. GM=false: store
// half2 into smem obS; GM=true: convert and store float2 into gmem obG.
// rxlo/rxhi even. x edge clamp folded into PRMT selectors; y clamp read-side.
template <bool GM>
__device__ __forceinline__ void do_region(const __half* __restrict__ cb,
                                          __half* __restrict__ obS,
                                          float* __restrict__ obG,
                                          int rxlo, int rxhi, int rylo, int ryhi,
                                          int tid, bool lb, bool rb, bool tbf, bool bbf) {
    int U = (rxhi - rxlo) >> 1;   // packed units per row (64..74)
    int S = NTHREADS / U;         // row strips (6..8)
    if (tid >= U * S) return;
    int ux = tid % U, sy = tid / U;
    int Hr = ryhi - rylo;
    int ylo = rylo + (sy * Hr) / S;        // balanced heights (diff <= 1)
    int yhi = rylo + ((sy + 1) * Hr) / S;
    if (ylo >= yhi) return;
    int x0 = rxlo + 2 * ux;

    bool fixL = lb && (x0 == 0);
    bool fixR = rb && (x0 + 2 == TW);
    int pLoff = fixL ? 0 : -2;
    int pRoff = fixR ? 0 : 2;
    uint32_t selL = fixL ? 0x1010u : 0x5432u;  // dup-low vs (hi16(a),lo16(b))
    uint32_t selR = fixR ? 0x3232u : 0x5432u;  // dup-high vs (hi16(a),lo16(b))

    int yclp = bbf ? (TH - 1) : (SROWS - OY - 1);   // unified read clamp (63/73)
    int ytop = tbf ? 0 : -0x40000000;               // top clamp (prologue only)

    __half2 lo[3], md[3], hi[3];
    {
        const __half* p0 = cb + max(ylo - 1, ytop) * SPH;
        uint32_t a = ld32(p0 + x0 + pLoff), b = ld32(p0 + x0), c = ld32(p0 + x0 + pRoff);
        sort3h(u2h(__byte_perm(a, b, selL)), u2h(b), u2h(__byte_perm(b, c, selR)),
               lo[0], md[0], hi[0]);
        const __half* p1 = cb + ylo * SPH;
        a = ld32(p1 + x0 + pLoff); b = ld32(p1 + x0); c = ld32(p1 + x0 + pRoff);
        sort3h(u2h(__byte_perm(a, b, selL)), u2h(b), u2h(__byte_perm(b, c, selR)),
               lo[1], md[1], hi[1]);
    }
    uint32_t raw[3];
    {
        const __half* p2 = cb + min(ylo + 1, yclp) * SPH;
        raw[0] = ld32(p2 + x0 + pLoff);
        raw[1] = ld32(p2 + x0);
        raw[2] = ld32(p2 + x0 + pRoff);
    }

    __half* opS = obS + ylo * SPH + x0;
    float* opG = obG + ylo * W + x0;
    int y = ylo;
    while (true) {
        row_step<0, 1, 2, GM>(cb + min(y + 2, yclp) * SPH, raw, opS, opG,
                              x0, pLoff, selL, pRoff, selR, lo, md, hi);
        if (++y >= yhi) break;
        opS += SPH; opG += W;
        row_step<1, 2, 0, GM>(cb + min(y + 2, yclp) * SPH, raw, opS, opG,
                              x0, pLoff, selL, pRoff, selR, lo, md, hi);
        if (++y >= yhi) break;
        opS += SPH; opG += W;
        row_step<2, 0, 1, GM>(cb + min(y + 2, yclp) * SPH, raw, opS, opG,
                              x0, pLoff, selL, pRoff, selR, lo, md, hi);
        if (++y >= yhi) break;
        opS += SPH; opG += W;
    }
}

extern __shared__ __half smemh[];

// One CTA = one 128x64 tile of one batch image; input converted once to fp16,
// all t_b iterations run packed 2-px/op in smem (ping-pong, margin-scheduled),
// final iteration converts back and streams to gmem. 51KB smem/CTA -> 3
// CTAs/SM (48 warps). Batches LPT-ordered through g_order via blockIdx.z.
__global__ void __launch_bounds__(NTHREADS, 3) fused_median_kernel(
    const float* __restrict__ x, float* __restrict__ out) {
    int b = g_order[blockIdx.z];
    int k = g_t[b];
    int gx0 = blockIdx.x * TW, gy0 = blockIdx.y * TH;
    const float* src = x + (size_t)b * NPIX;
    float* dstb = out + (size_t)b * NPIX + gy0 * W + gx0;

    int tid = threadIdx.x, lane = tid & 31, wrp = tid >> 5;  // 16 warps

    if (k == 0) {  // identity: exact fp32 copy (no fp16 rounding)
        for (int r = wrp; r < TH; r += NWARPS)
            *reinterpret_cast<float4*>(dstb + r * W + lane * 4) =
                *reinterpret_cast<const float4*>(src + (gy0 + r) * W + gx0 + lane * 4);
        return;
    }

    __half* bufA = smemh;
    __half* bufB = smemh + SMEM_BUFH;

    bool lb = (gx0 == 0), rb = (gx0 + TW == W);
    bool tb = (gy0 == 0), bb = (gy0 + TH == H);

    // Clamped initial load + f32->f16 convert, full pitch (cols 0..151 =
    // local x -12..139, rows 0..83 = local y -10..73). Covers all step-0 reads.
    if (!lb && !rb) {
        for (int r = wrp; r < SROWS; r += NWARPS) {
            int gy = min(max(gy0 + r - OY, 0), H - 1);
            const float2* rowp = reinterpret_cast<const float2*>(src + gy * W + gx0 - OXH);
            __half2* drow = reinterpret_cast<__half2*>(bufA + r * SPH);
            for (int c = lane; c < SPH / 2; c += 32) {
                float2 f = __ldg(rowp + c);
                drow[c] = __floats2half2_rn(f.x, f.y);
            }
        }
    } else {
        for (int r = wrp; r < SROWS; r += NWARPS) {
            int gy = min(max(gy0 + r - OY, 0), H - 1);
            const float* rowp = src + gy * W;
            for (int c = lane; c < SPH; c += 32)
                bufA[r * SPH + c] =
                    __float2half_rn(__ldg(rowp + min(max(gx0 + c - OXH, 0), W - 1)));
        }
    }
    __syncthreads();

    __half* cur = bufA;
    __half* nxt = bufB;
    for (int s = 0; s < k - 1; s++) {
        int m = k - 1 - s;              // margin still needed after this step
        int Xm = (m + 1) & ~1;          // even x margin >= m (stale cols provably
                                        // never contaminate the 128-wide core)
        int rxlo = lb ? 0 : -Xm, rxhi = rb ? TW : TW + Xm;
        int rylo = tb ? 0 : -m,  ryhi = bb ? TH : TH + m;

        do_region<false>(cur + OY * SPH + OXH, nxt + OY * SPH + OXH, nullptr,
                         rxlo, rxhi, rylo, ryhi, tid, lb, rb, tb, bb);
        __syncthreads();

        __half* t = cur; cur = nxt; nxt = t;
    }

    // Final iteration: exact 128x64 region, f16->f32 convert, float2 stores.
    do_region<true>(cur + OY * SPH + OXH, nullptr, dstb,
                    0, TW, 0, TH, tid, lb, rb, tb, bb);
}

extern "C" void kernel_launch(void* const* d_in, const int* in_sizes, int n_in,
                              void* d_out, int out_size) {
    const float* x = (const float*)d_in[0];
    const int* traw = (const int*)d_in[1];
    float* out = (float*)d_out;

    size_t smem_bytes = (size_t)2 * SMEM_BUFH * sizeof(__half);  // 51,072 B
    cudaFuncSetAttribute(fused_median_kernel,
                         cudaFuncAttributeMaxDynamicSharedMemorySize,
                         (int)smem_bytes);

    prep_t_kernel<<<1, 32>>>(traw);

    dim3 grid(W / TW, H / TH, BATCH);
    fused_median_kernel<<<grid, NTHREADS, smem_bytes>>>(x, out);
}

// round 17
// speedup vs baseline: 1.2151x; 1.2151x over previous
#include <cuda_runtime.h>

#define BATCH 32
#define H 512
#define W 512
#define NSTEPS 10
#define NPIX (H * W)
#define TW 128            // tile width
#define TH 64             // tile height
#define OX 12             // smem col of local x=0 (even -> 8B float2 alignment)
#define OY 10             // smem row of local y=0
#define SP 152            // smem pitch (floats), mult of 4
#define SROWS 84          // local y in [-10, 74)
#define SMEM_BUF (SROWS * SP)
#define NTHREADS 768      // 2 CTAs/SM -> 48 warps resident (75% occ ceiling)
#define NWARPS (NTHREADS / 32)

__device__ int g_t[BATCH];
__device__ int g_order[BATCH];  // batches sorted by descending t (LPT schedule)

// Normalize t into g_t as int32 (handles int64-vs-int32 materialization of the
// jax reference: if int64 little-endian with values in [0,10), all odd 32-bit
// words of the first 128 bytes are zero). Also builds the LPT batch order.
__global__ void prep_t_kernel(const int* __restrict__ traw) {
    int lane = threadIdx.x;  // 0..31
    int w = traw[lane];
    unsigned oddnz = __ballot_sync(0xffffffffu, ((lane & 1) != 0) && (w != 0));
    int v = (oddnz == 0u) ? traw[2 * lane] : w;
    v = min(max(v, 0), NSTEPS);
    g_t[lane] = v;

    int rank = 0;
#pragma unroll
    for (int j = 0; j < BATCH; j++) {
        int kj = __shfl_sync(0xffffffffu, v, j);
        rank += (kj > v) || (kj == v && j < lane);
    }
    g_order[rank] = lane;
}

__device__ __forceinline__ float med3(float a, float b, float c) {
    return fmaxf(fminf(a, b), fminf(fmaxf(a, b), c));
}

__device__ __forceinline__ void sort3(float a, float b, float c,
                                      float& lo, float& md, float& hi) {
    float s = fminf(a, b);
    float t = fmaxf(a, b);
    lo = fminf(s, c);
    hi = fmaxf(t, c);
    md = fmaxf(s, fminf(t, c));
}

// Raw 4-value window (x0-1..x0+2, x-clamped via offL/offR) of one smem row.
__device__ __forceinline__ float4 load_raw2(const float* __restrict__ p, int x0,
                                            int offL, int offR) {
    float2 c = *reinterpret_cast<const float2*>(p + x0);
    float4 r;
    r.x = p[x0 + offL];
    r.y = c.x;
    r.z = c.y;
    r.w = p[x0 + offR];
    return r;
}

// Sort a raw window into slot arrays (2 sorted triples).
__device__ __forceinline__ void sort_raw(const float4& v,
                                         float lo[2], float md[2], float hi[2]) {
    sort3(v.x, v.y, v.z, lo[0], md[0], hi[0]);
    sort3(v.y, v.z, v.w, lo[1], md[1], hi[1]);
}

// One output row, software-pipelined: consume prefetched raw into slot Cc,
// ISSUE the next row's loads (pn) early, then combine (A,B,Cc) and store.
// The prefetch LDS latency hides behind ~20 FMNMX of combine work.
template <int A, int B, int Cc>
__device__ __forceinline__ void row_step(const float* __restrict__ pn,
                                         float4& raw, float* __restrict__ op,
                                         int x0, int offL, int offR,
                                         float lo[3][2], float md[3][2], float hi[3][2]) {
    sort_raw(raw, lo[Cc], md[Cc], hi[Cc]);
    float4 nraw = load_raw2(pn, x0, offL, offR);  // independent: issues early
    float2 r;
    {
        float mn  = fmaxf(fmaxf(lo[A][0], lo[B][0]), lo[Cc][0]);  // max of mins
        float mx  = fminf(fminf(hi[A][0], hi[B][0]), hi[Cc][0]);  // min of maxs
        float mdv = med3(md[A][0], md[B][0], md[Cc][0]);          // med of meds
        r.x = med3(mn, mdv, mx);                                  // median9
    }
    {
        float mn  = fmaxf(fmaxf(lo[A][1], lo[B][1]), lo[Cc][1]);
        float mx  = fminf(fminf(hi[A][1], hi[B][1]), hi[Cc][1]);
        float mdv = med3(md[A][1], md[B][1], md[Cc][1]);
        r.y = med3(mn, mdv, mx);
    }
    *reinterpret_cast<float2*>(op) = r;
    raw = nraw;
}

// Median-filter region [rxlo,rxhi)x[rylo,ryhi) from smem cb into ob (pitch
// opitch; smem or gmem). rxlo/rxhi even. Image-border clamping is read-side.
// Over-prefetch past the strip end reads clamped, valid, finite smem rows
// (all rows <= 73 exist) and is discarded.
__device__ __forceinline__ void do_region(const float* __restrict__ cb,
                                          float* __restrict__ ob, int opitch,
                                          int rxlo, int rxhi, int rylo, int ryhi,
                                          int tid, bool lb, bool rb, bool tbf, bool bbf) {
    int U = (rxhi - rxlo) >> 1;   // 2-wide units per row (64..74)
    int S = NTHREADS / U;         // row strips (10..12)
    if (tid >= U * S) return;
    int ux = tid % U, sy = tid / U;
    int Hr = ryhi - rylo;
    int ylo = rylo + (sy * Hr) / S;        // balanced heights (diff <= 1)
    int yhi = rylo + ((sy + 1) * Hr) / S;
    if (ylo >= yhi) return;
    int x0 = rxlo + 2 * ux;
    int offL = (lb && x0 == 0) ? 0 : -1;            // x edge clamp, free
    int offR = (rb && x0 + 2 == TW) ? 1 : 2;
    int yclp = bbf ? (TH - 1) : (SROWS - OY - 1);   // unified read clamp (63/73)
    int ytop = tbf ? 0 : -0x40000000;               // top clamp (prologue only)

    float lo[3][2], md[3][2], hi[3][2];
    sort_raw(load_raw2(cb + max(ylo - 1, ytop) * SP, x0, offL, offR),
             lo[0], md[0], hi[0]);
    sort_raw(load_raw2(cb + ylo * SP, x0, offL, offR),
             lo[1], md[1], hi[1]);
    float4 raw = load_raw2(cb + min(ylo + 1, yclp) * SP, x0, offL, offR);

    float* op = ob + ylo * opitch + x0;
    int y = ylo;
    while (true) {
        row_step<0, 1, 2>(cb + min(y + 2, yclp) * SP, raw, op, x0, offL, offR, lo, md, hi);
        if (++y >= yhi) break;
        op += opitch;
        row_step<1, 2, 0>(cb + min(y + 2, yclp) * SP, raw, op, x0, offL, offR, lo, md, hi);
        if (++y >= yhi) break;
        op += opitch;
        row_step<2, 0, 1>(cb + min(y + 2, yclp) * SP, raw, op, x0, offL, offR, lo, md, hi);
        if (++y >= yhi) break;
        op += opitch;
    }
}

extern __shared__ float smem[];

// One CTA = one 128x64 tile of one batch image; all t_b iterations in smem
// (ping-pong), margin-scheduled; final iteration streams straight to gmem.
// 102KB smem/CTA -> 2 CTAs/SM; 768 threads -> 48 resident warps.
// Batches are LPT-ordered through g_order via blockIdx.z.
__global__ void __launch_bounds__(NTHREADS, 2) fused_median_kernel(
    const float* __restrict__ x, float* __restrict__ out) {
    int b = g_order[blockIdx.z];
    int k = g_t[b];
    int gx0 = blockIdx.x * TW, gy0 = blockIdx.y * TH;
    const float* src = x + (size_t)b * NPIX;
    float* dstb = out + (size_t)b * NPIX + gy0 * W + gx0;

    int tid = threadIdx.x, lane = tid & 31, wrp = tid >> 5;  // 24 warps

    if (k == 0) {  // identity: copy tile
        for (int r = wrp; r < TH; r += NWARPS)
            *reinterpret_cast<float4*>(dstb + r * W + lane * 4) =
                *reinterpret_cast<const float4*>(src + (gy0 + r) * W + gx0 + lane * 4);
        return;
    }

    float* bufA = smem;
    float* bufB = smem + SMEM_BUF;

    bool lb = (gx0 == 0), rb = (gx0 + TW == W);
    bool tb = (gy0 == 0), bb = (gy0 + TH == H);

    // Clamped initial load, full pitch (cols 0..151 = local x -12..139,
    // rows 0..83 = local y -10..73). Covers all step-0 reads.
    if (!lb && !rb) {
        // interior-x: no x clamp needed -> coalesced float2 loads
        for (int r = wrp; r < SROWS; r += NWARPS) {
            int gy = min(max(gy0 + r - OY, 0), H - 1);
            const float2* rowp = reinterpret_cast<const float2*>(src + gy * W + gx0 - OX);
            float2* drow = reinterpret_cast<float2*>(bufA + r * SP);
            for (int c = lane; c < SP / 2; c += 32)
                drow[c] = __ldg(rowp + c);
        }
    } else {
        for (int r = wrp; r < SROWS; r += NWARPS) {
            int gy = min(max(gy0 + r - OY, 0), H - 1);
            const float* rowp = src + gy * W;
            for (int c = lane; c < SP; c += 32)
                bufA[r * SP + c] = __ldg(rowp + min(max(gx0 + c - OX, 0), W - 1));
        }
    }
    __syncthreads();

    float* cur = bufA;
    float* nxt = bufB;
    for (int s = 0; s < k - 1; s++) {
        int m = k - 1 - s;              // margin still needed after this step
        int Xm = (m + 2) & ~1;          // even x margin, >= m+1 (stale-proof)
        int rxlo = lb ? 0 : -Xm, rxhi = rb ? TW : TW + Xm;
        int rylo = tb ? 0 : -m,  ryhi = bb ? TH : TH + m;

        do_region(cur + OY * SP + OX, nxt + OY * SP + OX, SP,
                  rxlo, rxhi, rylo, ryhi, tid, lb, rb, tb, bb);
        __syncthreads();

        float* t = cur; cur = nxt; nxt = t;
    }

    // Final iteration: exact 128x64 region, float2 stores to gmem, real
    // border flags (clamping is read-side).
    do_region(cur + OY * SP + OX, dstb, W, 0, TW, 0, TH, tid, lb, rb, tb, bb);
}

extern "C" void kernel_launch(void* const* d_in, const int* in_sizes, int n_in,
                              void* d_out, int out_size) {
    const float* x = (const float*)d_in[0];
    const int* traw = (const int*)d_in[1];
    float* out = (float*)d_out;

    size_t smem_bytes = (size_t)2 * SMEM_BUF * sizeof(float);  // 102,144 B
    cudaFuncSetAttribute(fused_median_kernel,
                         cudaFuncAttributeMaxDynamicSharedMemorySize,
                         (int)smem_bytes);

    prep_t_kernel<<<1, 32>>>(traw);

    dim3 grid(W / TW, H / TH, BATCH);
    fused_median_kernel<<<grid, NTHREADS, smem_bytes>>>(x, out);
}